// round 7
// baseline (speedup 1.0000x reference)
#include <cuda_runtime.h>
#include <math.h>

#define BB   16
#define SS   1024
#define EE   256
#define HH   256
#define G4   1024
#define WT_  256

// ---------- static scratch ----------
__device__ float g_Af[(size_t)BB * SS * G4];
__device__ float g_Ab[(size_t)BB * SS * G4];
__device__ float g_G [(size_t)BB * SS * G4];
__device__ float g_hn[(size_t)BB * SS * HH];
__device__ float g_hb[(size_t)BB * SS * HH];
__device__ float g_P [(size_t)BB * SS * WT_];
__device__ float g_b3[(size_t)BB * SS * WT_];
__device__ float g_WTf[G4 * HH];
__device__ float g_WTb[G4 * HH];
__device__ float g_WTd[G4 * HH];

// ---------- helpers ----------
__device__ __forceinline__ unsigned long long fma2(unsigned long long a,
                                                   unsigned long long b,
                                                   unsigned long long c) {
    unsigned long long d;
    asm("fma.rn.f32x2 %0, %1, %2, %3;" : "=l"(d) : "l"(a), "l"(b), "l"(c));
    return d;
}
__device__ __forceinline__ unsigned long long splat2(float a) {
    unsigned long long d; unsigned int u = __float_as_uint(a);
    asm("mov.b64 %0, {%1, %1};" : "=l"(d) : "r"(u));
    return d;
}
__device__ __forceinline__ float2 unpk(unsigned long long v) {
    float2 r;
    asm("mov.b64 {%0, %1}, %2;" : "=f"(r.x), "=f"(r.y) : "l"(v));
    return r;
}
__device__ __forceinline__ float sigf(float x) { return 1.0f / (1.0f + expf(-x)); }

__device__ __forceinline__ unsigned int smem_u32(const void* p) {
    unsigned int a;
    asm("{ .reg .u64 t; cvta.to.shared.u64 t, %1; cvt.u32.u64 %0, t; }" : "=r"(a) : "l"(p));
    return a;
}
__device__ __forceinline__ void st_cluster_f32(unsigned int addr, unsigned int rank, float v) {
    unsigned int ra;
    asm volatile("mapa.shared::cluster.u32 %0, %1, %2;" : "=r"(ra) : "r"(addr), "r"(rank));
    asm volatile("st.shared::cluster.f32 [%0], %1;" :: "r"(ra), "f"(v) : "memory");
}
__device__ __forceinline__ void cluster_sync() {
    asm volatile("barrier.cluster.arrive.aligned;" ::: "memory");
    asm volatile("barrier.cluster.wait.aligned;"   ::: "memory");
}
__device__ __forceinline__ void mbar_init(unsigned int addr, unsigned int cnt) {
    asm volatile("mbarrier.init.shared.b64 [%0], %1;" :: "r"(addr), "r"(cnt) : "memory");
}
__device__ __forceinline__ void fence_cluster() {
    asm volatile("fence.acq_rel.cluster;" ::: "memory");
}
__device__ __forceinline__ void mbar_arrive_remote(unsigned int addr, unsigned int rank) {
    unsigned int ra;
    asm volatile("mapa.shared::cluster.u32 %0, %1, %2;" : "=r"(ra) : "r"(addr), "r"(rank));
    asm volatile("mbarrier.arrive.release.cluster.shared::cluster.b64 _, [%0];"
                 :: "r"(ra) : "memory");
}
__device__ __forceinline__ void mbar_wait_acq(unsigned int addr, unsigned int parity) {
    asm volatile(
        "{\n\t"
        ".reg .pred P;\n\t"
        "WAITL%=:\n\t"
        "mbarrier.try_wait.parity.acquire.cluster.shared::cta.b64 P, [%0], %1, 0x989680;\n\t"
        "@P bra.uni WDONE%=;\n\t"
        "bra.uni WAITL%=;\n\t"
        "WDONE%=:\n\t"
        "}"
        :: "r"(addr), "r"(parity) : "memory");
}

// ---------- transpose [256,1024] -> [1024,256] ----------
__global__ void transpose_w(const float* __restrict__ in, float* __restrict__ out) {
    __shared__ float tile[32][33];
    int x = blockIdx.x * 32 + threadIdx.x;
    int y = blockIdx.y * 32 + threadIdx.y;
    tile[threadIdx.y][threadIdx.x] = in[y * G4 + x];
    __syncthreads();
    int ox = blockIdx.y * 32 + threadIdx.x;
    int oy = blockIdx.x * 32 + threadIdx.y;
    out[oy * HH + ox] = tile[threadIdx.x][threadIdx.y];
}

// ---------- multi-segment SGEMM, double-buffered ----------
__global__ __launch_bounds__(256, 2)
void sgemm_ms(const float* __restrict__ A0, const float* __restrict__ A1,
              const float* __restrict__ A2,
              const float* __restrict__ B0, const float* __restrict__ B1,
              const float* __restrict__ B2,
              float* __restrict__ C, int M, int N, int nseg) {
    __shared__ __align__(16) float As[2][16][128];
    __shared__ __align__(16) float Bs[2][16][128];
    int tid = threadIdx.x;
    int m0 = blockIdx.y * 128, n0 = blockIdx.x * 128;
    int tr = tid >> 4, tc = tid & 15;
    int rowA = m0 + tr * 8, colB = n0 + tc * 8;
    int rA = tid >> 2, cA = (tid & 3) * 4;
    int rB = tid >> 5, cB = (tid & 31) * 4;

    unsigned long long acc[8][4];
#pragma unroll
    for (int i = 0; i < 8; i++)
#pragma unroll
        for (int p2 = 0; p2 < 4; p2++) acc[i][p2] = 0ull;

    int total = nseg * 16;
    float4 la0, la1, lb0, lb1;

#define LD_IT(IT)                                                              \
    {   int seg = (IT) >> 4, k0 = ((IT) & 15) << 4;                            \
        const float* Aseg = seg == 0 ? A0 : (seg == 1 ? A1 : A2);              \
        const float* Bseg = seg == 0 ? B0 : (seg == 1 ? B1 : B2);              \
        const float* Ap = Aseg + (size_t)(m0 + rA) * 256 + k0 + cA;            \
        la0 = *(const float4*)Ap;                                              \
        la1 = *(const float4*)(Ap + 64 * 256);                                 \
        const float* Bp = Bseg + (size_t)(k0 + rB) * N + n0 + cB;              \
        lb0 = *(const float4*)Bp;                                              \
        lb1 = *(const float4*)(Bp + 8 * N); }
#define ST_IT(P)                                                               \
    {   As[P][cA + 0][rA] = la0.x; As[P][cA + 1][rA] = la0.y;                  \
        As[P][cA + 2][rA] = la0.z; As[P][cA + 3][rA] = la0.w;                  \
        As[P][cA + 0][rA + 64] = la1.x; As[P][cA + 1][rA + 64] = la1.y;        \
        As[P][cA + 2][rA + 64] = la1.z; As[P][cA + 3][rA + 64] = la1.w;        \
        *(float4*)&Bs[P][rB][cB] = lb0;                                        \
        *(float4*)&Bs[P][rB + 8][cB] = lb1; }

    LD_IT(0); ST_IT(0);
    __syncthreads();
    int p = 0;
    for (int it = 0; it < total; ++it) {
        if (it + 1 < total) LD_IT(it + 1);
#pragma unroll
        for (int kk = 0; kk < 16; kk++) {
            float4 a0 = *(const float4*)&As[p][kk][tr * 8];
            float4 a1 = *(const float4*)&As[p][kk][tr * 8 + 4];
            ulonglong2 b0 = *(const ulonglong2*)&Bs[p][kk][tc * 8];
            ulonglong2 b1 = *(const ulonglong2*)&Bs[p][kk][tc * 8 + 4];
            float av[8] = {a0.x, a0.y, a0.z, a0.w, a1.x, a1.y, a1.z, a1.w};
#pragma unroll
            for (int i = 0; i < 8; i++) {
                unsigned long long s = splat2(av[i]);
                acc[i][0] = fma2(s, b0.x, acc[i][0]);
                acc[i][1] = fma2(s, b0.y, acc[i][1]);
                acc[i][2] = fma2(s, b1.x, acc[i][2]);
                acc[i][3] = fma2(s, b1.y, acc[i][3]);
            }
        }
        if (it + 1 < total) ST_IT(1 - p);
        __syncthreads();
        p ^= 1;
    }
#pragma unroll
    for (int i = 0; i < 8; i++) {
        float* cp = C + (size_t)(rowA + i) * N + colB;
#pragma unroll
        for (int p2 = 0; p2 < 4; p2++) {
            float2 v = unpk(acc[i][p2]);
            cp[2 * p2] = v.x; cp[2 * p2 + 1] = v.y;
        }
    }
#undef LD_IT
#undef ST_IT
}

// ======================================================================
// Weight-stationary cluster LSTMs: 8 CTAs/cluster, 512 thr/CTA,
// mbarrier all-to-all h exchange (no barrier.cluster in the step loop).
// ======================================================================

// ---------- encoder: 16 clusters (dir x batch-pair), 2 batches each ----------
__global__ __launch_bounds__(512, 1) __cluster_dims__(8, 1, 1)
void lstm_enc(const float* __restrict__ Af, const float* __restrict__ Ab,
              const float* __restrict__ WTf, const float* __restrict__ WTb,
              const float* __restrict__ bf, const float* __restrict__ bbp,
              float* __restrict__ hn, float* __restrict__ hb) {
    int r   = blockIdx.x & 7;
    int cid = blockIdx.x >> 3;
    int d   = cid >> 3;
    int pr  = cid & 7;
    int b0 = 2 * pr, b1 = 2 * pr + 1;
    const float* A    = d ? Ab  : Af;
    const float* WT   = d ? WTb : WTf;
    const float* bias = d ? bbp : bf;
    float* H          = d ? hb  : hn;

    __shared__ __align__(16) float hs[2][2][HH];   // [buf][bat][k]
    __shared__ float zp[2][4][128];                // [bat][quarter][localrow]
    __shared__ unsigned long long mb;

    int tid = threadIdx.x;
    int q  = tid >> 7;
    int lr = tid & 127;
    int row = (lr >> 5) * 256 + r * 32 + (lr & 31);

    unsigned long long w2[32];
    {
        const ulonglong2* wp = (const ulonglong2*)(WT + (size_t)row * 256 + q * 64);
#pragma unroll
        for (int i = 0; i < 16; i++) { ulonglong2 v = wp[i]; w2[2*i] = v.x; w2[2*i+1] = v.y; }
    }

    bool upd = tid < 64;
    int ub = tid >> 5, uk = tid & 31;
    int bq = ub ? b1 : b0;
    float c = 0.f;
    float bias4[4];
    if (upd) {
#pragma unroll
        for (int g = 0; g < 4; g++) bias4[g] = bias[g * 256 + r * 32 + uk];
    }
    hs[0][tid >> 8][tid & 255] = 0.f;
    unsigned int mba = smem_u32(&mb);
    if (tid == 0) mbar_init(mba, 8);
    __syncthreads();
    cluster_sync();   // all mbarriers + hs[0] ready cluster-wide

    int p = 0;
    unsigned int ph = 0;
    for (int step = 0; step < SS; ++step) {
        int t = d ? (SS - 1 - step) : step;
        float av[4];
        if (upd) {   // prefetch gate inputs; hidden under the dot phase
            const float* Ap = A + ((size_t)(bq * SS + t)) * G4 + r * 32 + uk;
#pragma unroll
            for (int g = 0; g < 4; g++) av[g] = __ldg(Ap + g * 256);
        }

        unsigned long long a0a = 0ull, a0b = 0ull, a1a = 0ull, a1b = 0ull;
        const ulonglong2* h0 = (const ulonglong2*)&hs[p][0][q * 64];
        const ulonglong2* h1 = (const ulonglong2*)&hs[p][1][q * 64];
#pragma unroll
        for (int i = 0; i < 16; i++) {
            ulonglong2 x0 = h0[i], x1 = h1[i];
            a0a = fma2(x0.x, w2[2*i], a0a); a0b = fma2(x0.y, w2[2*i+1], a0b);
            a1a = fma2(x1.x, w2[2*i], a1a); a1b = fma2(x1.y, w2[2*i+1], a1b);
        }
        float2 u0 = unpk(fma2(splat2(1.f), a0a, a0b));
        float2 u1 = unpk(fma2(splat2(1.f), a1a, a1b));
        zp[0][q][lr] = u0.x + u0.y;
        zp[1][q][lr] = u1.x + u1.y;
        __syncthreads();

        if (upd) {
            float z[4];
#pragma unroll
            for (int g = 0; g < 4; g++) {
                int l = g * 32 + uk;
                z[g] = zp[ub][0][l] + zp[ub][1][l] + zp[ub][2][l] + zp[ub][3][l]
                     + av[g] + bias4[g];
            }
            float iv = sigf(z[0]), fv = sigf(z[1]);
            float gv = tanhf(z[2]), ov = sigf(z[3]);
            c = fv * c + iv * gv;
            float h = ov * tanhf(c);
            int k = r * 32 + uk;
            unsigned int base = smem_u32(&hs[1 - p][ub][k]);
#pragma unroll
            for (int cta = 0; cta < 8; cta++) st_cluster_f32(base, cta, h);
            H[((size_t)(bq * SS + t)) * HH + k] = h;
            asm volatile("bar.sync 1, 64;" ::: "memory");   // order both updater warps
            if (tid < 8) {
                fence_cluster();
                mbar_arrive_remote(mba, (unsigned)tid);
            }
        }
        mbar_wait_acq(mba, ph);
        ph ^= 1;
        p ^= 1;
    }
}

// ---------- decoder: 16 clusters, ONE batch each (128 CTAs) ----------
__global__ __launch_bounds__(512, 1) __cluster_dims__(8, 1, 1)
void lstm_dec(const float* __restrict__ G, const float* __restrict__ WT,
              const float* __restrict__ bias, const float* __restrict__ hn,
              const float* __restrict__ P, const float* __restrict__ b3,
              const float* __restrict__ W4, const float* __restrict__ vt1,
              float* __restrict__ out) {
    int r = blockIdx.x & 7;
    int b = blockIdx.x >> 3;

    __shared__ __align__(16) float hs[2][HH];
    __shared__ float zp[4][128];
    __shared__ __align__(16) float qp[2][WT_];
    __shared__ __align__(16) float qv[WT_];
    __shared__ __align__(16) float vs[WT_];
    __shared__ float rs[16];
    __shared__ int   ri[16];
    __shared__ int   bond_s;
    __shared__ unsigned long long mb;

    int tid = threadIdx.x;
    int q  = tid >> 7;
    int lr = tid & 127;
    int row = (lr >> 5) * 256 + r * 32 + (lr & 31);

    unsigned long long w2[32];
    {
        const ulonglong2* wp = (const ulonglong2*)(WT + (size_t)row * 256 + q * 64);
#pragma unroll
        for (int i = 0; i < 16; i++) { ulonglong2 v = wp[i]; w2[2*i] = v.x; w2[2*i+1] = v.y; }
    }

    bool upd = tid < 32;
    float c = 0.f;
    float bias4[4];
    if (upd) {
#pragma unroll
        for (int g = 0; g < 4; g++) bias4[g] = bias[g * 256 + r * 32 + tid];
        c = hn[((size_t)(b * SS + SS - 1)) * HH + r * 32 + tid];
    }
    if (tid < 256) { hs[0][tid] = 0.f; vs[tid] = vt1[tid]; }
    if (tid == 0) bond_s = 0;
    if (r == 0)
        for (int i = tid; i < SS; i += 512) out[(size_t)i * BB + b] = 0.f;
    unsigned int mba = smem_u32(&mb);
    if (tid == 0) mbar_init(mba, 8);
    __syncthreads();
    cluster_sync();

    int p = 0;
    unsigned int ph = 0;
    for (int t = 0; t < SS; ++t) {
        float gv4[4];
        if (upd) {
            if (t > 0) {
                const float* Gp = G + ((size_t)(b * SS + t - 1)) * G4 + r * 32 + tid;
#pragma unroll
                for (int g = 0; g < 4; g++) gv4[g] = __ldg(Gp + g * 256);
            } else {
#pragma unroll
                for (int g = 0; g < 4; g++) gv4[g] = 0.f;
            }
        }

        unsigned long long aa = 0ull, ab2 = 0ull;
        const ulonglong2* h0 = (const ulonglong2*)&hs[p][q * 64];
#pragma unroll
        for (int i = 0; i < 16; i++) {
            ulonglong2 x0 = h0[i];
            aa  = fma2(x0.x, w2[2*i], aa);
            ab2 = fma2(x0.y, w2[2*i+1], ab2);
        }
        float2 u = unpk(fma2(splat2(1.f), aa, ab2));
        zp[q][lr] = u.x + u.y;
        __syncthreads();

        if (upd) {
            float z[4];
#pragma unroll
            for (int g = 0; g < 4; g++) {
                int l = g * 32 + tid;
                z[g] = zp[0][l] + zp[1][l] + zp[2][l] + zp[3][l] + gv4[g] + bias4[g];
            }
            float iv = sigf(z[0]), fv = sigf(z[1]);
            float gg = tanhf(z[2]), ov = sigf(z[3]);
            c = fv * c + iv * gg;
            float h = ov * tanhf(c);
            int k = r * 32 + tid;
            unsigned int base = smem_u32(&hs[1 - p][k]);
#pragma unroll
            for (int cta = 0; cta < 8; cta++) st_cluster_f32(base, cta, h);
            __syncwarp();
            if (tid < 8) {
                fence_cluster();
                mbar_arrive_remote(mba, (unsigned)tid);
            }
        }
        mbar_wait_acq(mba, ph);
        ph ^= 1;
        p ^= 1;

        if (t == bond_s) {   // decision step (replicated in all 8 CTAs)
            {
                int j = tid & 255, kh = tid >> 8;
                const float* w4p = W4 + (size_t)(kh * 128) * WT_ + j;
                const float* hh = &hs[p][kh * 128];
                float acc = 0.f;
#pragma unroll 4
                for (int k = 0; k < 128; ++k) acc += hh[k] * w4p[(size_t)k * WT_];
                qp[kh][j] = acc;
            }
            __syncthreads();
            if (tid < 256)
                qv[tid] = qp[0][tid] + qp[1][tid] + b3[((size_t)(b * SS + t)) * WT_ + tid];
            __syncthreads();
            int wp = tid >> 5, lane = tid & 31;
            float best = -3.4e38f; int bi = 0x7fffffff;
            for (int pos = t + wp; pos < SS; pos += 16) {
                const float* Pr = P + ((size_t)(b * SS + pos)) * WT_;
                float4 p0 = *(const float4*)(Pr + lane * 4);
                float4 p1 = *(const float4*)(Pr + 128 + lane * 4);
                const float4 q0 = *(const float4*)(qv + lane * 4);
                const float4 q1 = *(const float4*)(qv + 128 + lane * 4);
                const float4 v0 = *(const float4*)(vs + lane * 4);
                const float4 v1 = *(const float4*)(vs + 128 + lane * 4);
                float s = v0.x * tanhf(p0.x + q0.x) + v0.y * tanhf(p0.y + q0.y)
                        + v0.z * tanhf(p0.z + q0.z) + v0.w * tanhf(p0.w + q0.w)
                        + v1.x * tanhf(p1.x + q1.x) + v1.y * tanhf(p1.y + q1.y)
                        + v1.z * tanhf(p1.z + q1.z) + v1.w * tanhf(p1.w + q1.w);
#pragma unroll
                for (int off = 16; off > 0; off >>= 1)
                    s += __shfl_down_sync(0xffffffffu, s, off);
                s = __shfl_sync(0xffffffffu, s, 0);
                if (s > best) { best = s; bi = pos; }   // increasing pos: ties keep first
            }
            if (lane == 0) { rs[wp] = best; ri[wp] = bi; }
            __syncthreads();
            if (tid == 0) {
                float bb = rs[0]; int bx = ri[0];
#pragma unroll
                for (int w = 1; w < 16; w++)
                    if (rs[w] > bb || (rs[w] == bb && ri[w] < bx)) { bb = rs[w]; bx = ri[w]; }
                bond_s = bx;
                if (r == 0) out[(size_t)bx * BB + b] = 1.0f;
            }
            __syncthreads();
        }
    }
}

extern "C" void kernel_launch(void* const* d_in, const int* in_sizes, int n_in,
                              void* d_out, int out_size) {
    const float* x        = (const float*)d_in[0];
    const float* eWih_f   = (const float*)d_in[1];
    const float* eWhh_f   = (const float*)d_in[2];
    const float* eb_f     = (const float*)d_in[3];
    const float* eWih_b   = (const float*)d_in[4];
    const float* eWhh_b   = (const float*)d_in[5];
    const float* eb_b     = (const float*)d_in[6];
    const float* dWih     = (const float*)d_in[7];
    const float* dWhh     = (const float*)d_in[8];
    const float* db       = (const float*)d_in[9];
    const float* W1       = (const float*)d_in[10];
    const float* W2       = (const float*)d_in[11];
    const float* W3       = (const float*)d_in[12];
    const float* W4       = (const float*)d_in[13];
    const float* vt1      = (const float*)d_in[14];
    float* out = (float*)d_out;

    float *Af, *Ab, *G, *hn, *hb, *P, *b3, *WTf, *WTb, *WTd;
    cudaGetSymbolAddress((void**)&Af,  g_Af);
    cudaGetSymbolAddress((void**)&Ab,  g_Ab);
    cudaGetSymbolAddress((void**)&G,   g_G);
    cudaGetSymbolAddress((void**)&hn,  g_hn);
    cudaGetSymbolAddress((void**)&hb,  g_hb);
    cudaGetSymbolAddress((void**)&P,   g_P);
    cudaGetSymbolAddress((void**)&b3,  g_b3);
    cudaGetSymbolAddress((void**)&WTf, g_WTf);
    cudaGetSymbolAddress((void**)&WTb, g_WTb);
    cudaGetSymbolAddress((void**)&WTd, g_WTd);

    dim3 tb(32, 32), tg(G4 / 32, HH / 32);
    transpose_w<<<tg, tb>>>(eWhh_f, WTf);
    transpose_w<<<tg, tb>>>(eWhh_b, WTb);
    transpose_w<<<tg, tb>>>(dWhh,   WTd);

    const int M = BB * SS;
    sgemm_ms<<<dim3(G4 / 128, M / 128), 256>>>(x, 0, 0, eWih_f, 0, 0, Af, M, G4, 1);
    sgemm_ms<<<dim3(G4 / 128, M / 128), 256>>>(x, 0, 0, eWih_b, 0, 0, Ab, M, G4, 1);
    sgemm_ms<<<dim3(WT_ / 128, M / 128), 256>>>(x, 0, 0, W3, 0, 0, b3, M, WT_, 1);

    lstm_enc<<<128, 512>>>(Af, Ab, WTf, WTb, eb_f, eb_b, hn, hb);

    sgemm_ms<<<dim3(G4 / 128, M / 128), 256>>>(x, hn, 0, dWih, dWih + EE * G4, 0,
                                               G, M, G4, 2);
    sgemm_ms<<<dim3(WT_ / 128, M / 128), 256>>>(hn, hb, x, W1, W1 + HH * WT_, W2,
                                                P, M, WT_, 3);

    lstm_dec<<<128, 512>>>(G, WTd, db, hn, P, b3, W4, vt1, out);
}

// round 8
// speedup vs baseline: 1.2942x; 1.2942x over previous
#include <cuda_runtime.h>
#include <math.h>

#define BB   16
#define SS   1024
#define EE   256
#define HH   256
#define G4   1024
#define WT_  256

// ---------- static scratch ----------
__device__ float g_Af[(size_t)BB * SS * G4];
__device__ float g_Ab[(size_t)BB * SS * G4];
__device__ float g_G [(size_t)BB * SS * G4];
__device__ float g_hn[(size_t)BB * SS * HH];
__device__ float g_hb[(size_t)BB * SS * HH];
__device__ float g_P [(size_t)BB * SS * WT_];
__device__ float g_b3[(size_t)BB * SS * WT_];
__device__ float g_WTf[G4 * HH];
__device__ float g_WTb[G4 * HH];
__device__ float g_WTd[G4 * HH];

// ---------- helpers ----------
__device__ __forceinline__ unsigned long long fma2(unsigned long long a,
                                                   unsigned long long b,
                                                   unsigned long long c) {
    unsigned long long d;
    asm("fma.rn.f32x2 %0, %1, %2, %3;" : "=l"(d) : "l"(a), "l"(b), "l"(c));
    return d;
}
__device__ __forceinline__ unsigned long long splat2(float a) {
    unsigned long long d; unsigned int u = __float_as_uint(a);
    asm("mov.b64 %0, {%1, %1};" : "=l"(d) : "r"(u));
    return d;
}
__device__ __forceinline__ float2 unpk(unsigned long long v) {
    float2 r;
    asm("mov.b64 {%0, %1}, %2;" : "=f"(r.x), "=f"(r.y) : "l"(v));
    return r;
}
__device__ __forceinline__ float sigf(float x) { return 1.0f / (1.0f + expf(-x)); }

__device__ __forceinline__ unsigned int smem_u32(const void* p) {
    unsigned int a;
    asm("{ .reg .u64 t; cvta.to.shared.u64 t, %1; cvt.u32.u64 %0, t; }" : "=r"(a) : "l"(p));
    return a;
}
__device__ __forceinline__ void st_cluster_f32(unsigned int addr, unsigned int rank, float v) {
    unsigned int ra;
    asm volatile("mapa.shared::cluster.u32 %0, %1, %2;" : "=r"(ra) : "r"(addr), "r"(rank));
    asm volatile("st.shared::cluster.f32 [%0], %1;" :: "r"(ra), "f"(v) : "memory");
}
__device__ __forceinline__ void cluster_sync() {
    asm volatile("barrier.cluster.arrive.aligned;" ::: "memory");
    asm volatile("barrier.cluster.wait.aligned;"   ::: "memory");
}
__device__ __forceinline__ void cluster_arrive() {
    asm volatile("barrier.cluster.arrive.aligned;" ::: "memory");
}
__device__ __forceinline__ void cluster_wait() {
    asm volatile("barrier.cluster.wait.aligned;" ::: "memory");
}

// ---------- transpose [256,1024] -> [1024,256] ----------
__global__ void transpose_w(const float* __restrict__ in, float* __restrict__ out) {
    __shared__ float tile[32][33];
    int x = blockIdx.x * 32 + threadIdx.x;
    int y = blockIdx.y * 32 + threadIdx.y;
    tile[threadIdx.y][threadIdx.x] = in[y * G4 + x];
    __syncthreads();
    int ox = blockIdx.y * 32 + threadIdx.x;
    int oy = blockIdx.x * 32 + threadIdx.y;
    out[oy * HH + ox] = tile[threadIdx.x][threadIdx.y];
}

// ---------- multi-segment SGEMM, double-buffered ----------
__global__ __launch_bounds__(256, 2)
void sgemm_ms(const float* __restrict__ A0, const float* __restrict__ A1,
              const float* __restrict__ A2,
              const float* __restrict__ B0, const float* __restrict__ B1,
              const float* __restrict__ B2,
              float* __restrict__ C, int M, int N, int nseg) {
    __shared__ __align__(16) float As[2][16][128];
    __shared__ __align__(16) float Bs[2][16][128];
    int tid = threadIdx.x;
    int m0 = blockIdx.y * 128, n0 = blockIdx.x * 128;
    int tr = tid >> 4, tc = tid & 15;
    int rowA = m0 + tr * 8, colB = n0 + tc * 8;
    int rA = tid >> 2, cA = (tid & 3) * 4;
    int rB = tid >> 5, cB = (tid & 31) * 4;

    unsigned long long acc[8][4];
#pragma unroll
    for (int i = 0; i < 8; i++)
#pragma unroll
        for (int p2 = 0; p2 < 4; p2++) acc[i][p2] = 0ull;

    int total = nseg * 16;
    float4 la0, la1, lb0, lb1;

#define LD_IT(IT)                                                              \
    {   int seg = (IT) >> 4, k0 = ((IT) & 15) << 4;                            \
        const float* Aseg = seg == 0 ? A0 : (seg == 1 ? A1 : A2);              \
        const float* Bseg = seg == 0 ? B0 : (seg == 1 ? B1 : B2);              \
        const float* Ap = Aseg + (size_t)(m0 + rA) * 256 + k0 + cA;            \
        la0 = *(const float4*)Ap;                                              \
        la1 = *(const float4*)(Ap + 64 * 256);                                 \
        const float* Bp = Bseg + (size_t)(k0 + rB) * N + n0 + cB;              \
        lb0 = *(const float4*)Bp;                                              \
        lb1 = *(const float4*)(Bp + 8 * N); }
#define ST_IT(P)                                                               \
    {   As[P][cA + 0][rA] = la0.x; As[P][cA + 1][rA] = la0.y;                  \
        As[P][cA + 2][rA] = la0.z; As[P][cA + 3][rA] = la0.w;                  \
        As[P][cA + 0][rA + 64] = la1.x; As[P][cA + 1][rA + 64] = la1.y;        \
        As[P][cA + 2][rA + 64] = la1.z; As[P][cA + 3][rA + 64] = la1.w;        \
        *(float4*)&Bs[P][rB][cB] = lb0;                                        \
        *(float4*)&Bs[P][rB + 8][cB] = lb1; }

    LD_IT(0); ST_IT(0);
    __syncthreads();
    int p = 0;
    for (int it = 0; it < total; ++it) {
        if (it + 1 < total) LD_IT(it + 1);
#pragma unroll
        for (int kk = 0; kk < 16; kk++) {
            float4 a0 = *(const float4*)&As[p][kk][tr * 8];
            float4 a1 = *(const float4*)&As[p][kk][tr * 8 + 4];
            ulonglong2 b0 = *(const ulonglong2*)&Bs[p][kk][tc * 8];
            ulonglong2 b1 = *(const ulonglong2*)&Bs[p][kk][tc * 8 + 4];
            float av[8] = {a0.x, a0.y, a0.z, a0.w, a1.x, a1.y, a1.z, a1.w};
#pragma unroll
            for (int i = 0; i < 8; i++) {
                unsigned long long s = splat2(av[i]);
                acc[i][0] = fma2(s, b0.x, acc[i][0]);
                acc[i][1] = fma2(s, b0.y, acc[i][1]);
                acc[i][2] = fma2(s, b1.x, acc[i][2]);
                acc[i][3] = fma2(s, b1.y, acc[i][3]);
            }
        }
        if (it + 1 < total) ST_IT(1 - p);
        __syncthreads();
        p ^= 1;
    }
#pragma unroll
    for (int i = 0; i < 8; i++) {
        float* cp = C + (size_t)(rowA + i) * N + colB;
#pragma unroll
        for (int p2 = 0; p2 < 4; p2++) {
            float2 v = unpk(acc[i][p2]);
            cp[2 * p2] = v.x; cp[2 * p2 + 1] = v.y;
        }
    }
#undef LD_IT
#undef ST_IT
}

// ======================================================================
// Weight-stationary cluster LSTMs (8 CTAs/cluster, 512 thr/CTA).
// R4 step structure + split cluster barrier (arrive at end of step,
// wait deferred past the next step's gate-input prefetch).
// ======================================================================

// ---------- encoder: 16 clusters (dir x batch-pair), 2 batches each ----------
__global__ __launch_bounds__(512, 1) __cluster_dims__(8, 1, 1)
void lstm_enc(const float* __restrict__ Af, const float* __restrict__ Ab,
              const float* __restrict__ WTf, const float* __restrict__ WTb,
              const float* __restrict__ bf, const float* __restrict__ bbp,
              float* __restrict__ hn, float* __restrict__ hb) {
    int r   = blockIdx.x & 7;
    int cid = blockIdx.x >> 3;
    int d   = cid >> 3;
    int pr  = cid & 7;
    int b0 = 2 * pr, b1 = 2 * pr + 1;
    const float* A    = d ? Ab  : Af;
    const float* WT   = d ? WTb : WTf;
    const float* bias = d ? bbp : bf;
    float* H          = d ? hb  : hn;

    __shared__ __align__(16) float hs[2][2][HH];   // [buf][bat][k]
    __shared__ float zp[2][4][128];                // [bat][quarter][localrow]

    int tid = threadIdx.x;
    int q  = tid >> 7;
    int lr = tid & 127;
    int row = (lr >> 5) * 256 + r * 32 + (lr & 31);

    unsigned long long w2[32];
    {
        const ulonglong2* wp = (const ulonglong2*)(WT + (size_t)row * 256 + q * 64);
#pragma unroll
        for (int i = 0; i < 16; i++) { ulonglong2 v = wp[i]; w2[2*i] = v.x; w2[2*i+1] = v.y; }
    }

    bool upd = tid < 64;
    int ub = tid >> 5, uk = tid & 31;
    int bq = ub ? b1 : b0;
    float c = 0.f;
    float bias4[4];
    if (upd) {
#pragma unroll
        for (int g = 0; g < 4; g++) bias4[g] = bias[g * 256 + r * 32 + uk];
    }
    hs[0][tid >> 8][tid & 255] = 0.f;
    __syncthreads();
    cluster_sync();   // hs[0] ready cluster-wide; no split barrier pending

    int p = 0;
    for (int step = 0; step < SS; ++step) {
        int t = d ? (SS - 1 - step) : step;
        float av[4];
        if (upd) {   // gate-input prefetch (no dependency on h)
            const float* Ap = A + ((size_t)(bq * SS + t)) * G4 + r * 32 + uk;
#pragma unroll
            for (int g = 0; g < 4; g++) av[g] = __ldg(Ap + g * 256);
        }
        if (step > 0) cluster_wait();   // h from previous step now visible

        unsigned long long a0a = 0ull, a0b = 0ull, a1a = 0ull, a1b = 0ull;
        const ulonglong2* h0 = (const ulonglong2*)&hs[p][0][q * 64];
        const ulonglong2* h1 = (const ulonglong2*)&hs[p][1][q * 64];
#pragma unroll
        for (int i = 0; i < 16; i++) {
            ulonglong2 x0 = h0[i], x1 = h1[i];
            a0a = fma2(x0.x, w2[2*i], a0a); a0b = fma2(x0.y, w2[2*i+1], a0b);
            a1a = fma2(x1.x, w2[2*i], a1a); a1b = fma2(x1.y, w2[2*i+1], a1b);
        }
        float2 u0 = unpk(fma2(splat2(1.f), a0a, a0b));
        float2 u1 = unpk(fma2(splat2(1.f), a1a, a1b));
        zp[0][q][lr] = u0.x + u0.y;
        zp[1][q][lr] = u1.x + u1.y;
        __syncthreads();

        if (upd) {
            float z[4];
#pragma unroll
            for (int g = 0; g < 4; g++) {
                int l = g * 32 + uk;
                z[g] = zp[ub][0][l] + zp[ub][1][l] + zp[ub][2][l] + zp[ub][3][l]
                     + av[g] + bias4[g];
            }
            float iv = sigf(z[0]), fv = sigf(z[1]);
            float gv = tanhf(z[2]), ov = sigf(z[3]);
            c = fv * c + iv * gv;
            float h = ov * tanhf(c);
            int k = r * 32 + uk;
            unsigned int base = smem_u32(&hs[1 - p][ub][k]);
#pragma unroll
            for (int cta = 0; cta < 8; cta++) st_cluster_f32(base, cta, h);
            H[((size_t)(bq * SS + t)) * HH + k] = h;
        }
        cluster_arrive();   // release: updaters after stores, others right away
        p ^= 1;
    }
    cluster_wait();         // drain final barrier before exit
}

// ---------- decoder: 16 clusters, ONE batch each (128 CTAs) ----------
__global__ __launch_bounds__(512, 1) __cluster_dims__(8, 1, 1)
void lstm_dec(const float* __restrict__ G, const float* __restrict__ WT,
              const float* __restrict__ bias, const float* __restrict__ hn,
              const float* __restrict__ P, const float* __restrict__ b3,
              const float* __restrict__ W4, const float* __restrict__ vt1,
              float* __restrict__ out) {
    int r = blockIdx.x & 7;
    int b = blockIdx.x >> 3;

    __shared__ __align__(16) float hs[2][HH];
    __shared__ float zp[4][128];
    __shared__ __align__(16) float qp[2][WT_];
    __shared__ __align__(16) float qv[WT_];
    __shared__ __align__(16) float vs[WT_];
    __shared__ float rs[16];
    __shared__ int   ri[16];
    __shared__ int   bond_s;

    int tid = threadIdx.x;
    int q  = tid >> 7;
    int lr = tid & 127;
    int row = (lr >> 5) * 256 + r * 32 + (lr & 31);

    unsigned long long w2[32];
    {
        const ulonglong2* wp = (const ulonglong2*)(WT + (size_t)row * 256 + q * 64);
#pragma unroll
        for (int i = 0; i < 16; i++) { ulonglong2 v = wp[i]; w2[2*i] = v.x; w2[2*i+1] = v.y; }
    }

    bool upd = tid < 32;
    float c = 0.f;
    float bias4[4];
    if (upd) {
#pragma unroll
        for (int g = 0; g < 4; g++) bias4[g] = bias[g * 256 + r * 32 + tid];
        c = hn[((size_t)(b * SS + SS - 1)) * HH + r * 32 + tid];
    }
    if (tid < 256) { hs[0][tid] = 0.f; vs[tid] = vt1[tid]; }
    if (tid == 0) bond_s = 0;
    if (r == 0)
        for (int i = tid; i < SS; i += 512) out[(size_t)i * BB + b] = 0.f;
    __syncthreads();
    cluster_sync();

    int p = 0;
    for (int t = 0; t < SS; ++t) {
        float gv4[4];
        if (upd) {
            if (t > 0) {
                const float* Gp = G + ((size_t)(b * SS + t - 1)) * G4 + r * 32 + tid;
#pragma unroll
                for (int g = 0; g < 4; g++) gv4[g] = __ldg(Gp + g * 256);
            } else {
#pragma unroll
                for (int g = 0; g < 4; g++) gv4[g] = 0.f;
            }
        }
        if (t > 0) {
            cluster_wait();                 // h_{t-1} visible cluster-wide
            if (t - 1 == bond_s) {          // deferred decision for step t-1
                int td = t - 1;
                {
                    int j = tid & 255, kh = tid >> 8;
                    const float* w4p = W4 + (size_t)(kh * 128) * WT_ + j;
                    const float* hh = &hs[p][kh * 128];
                    float acc = 0.f;
#pragma unroll 4
                    for (int k = 0; k < 128; ++k) acc += hh[k] * w4p[(size_t)k * WT_];
                    qp[kh][j] = acc;
                }
                __syncthreads();
                if (tid < 256)
                    qv[tid] = qp[0][tid] + qp[1][tid] + b3[((size_t)(b * SS + td)) * WT_ + tid];
                __syncthreads();
                int wp2 = tid >> 5, lane = tid & 31;
                float best = -3.4e38f; int bi = 0x7fffffff;
                for (int pos = td + wp2; pos < SS; pos += 16) {
                    const float* Pr = P + ((size_t)(b * SS + pos)) * WT_;
                    float4 p0 = *(const float4*)(Pr + lane * 4);
                    float4 p1 = *(const float4*)(Pr + 128 + lane * 4);
                    const float4 q0 = *(const float4*)(qv + lane * 4);
                    const float4 q1 = *(const float4*)(qv + 128 + lane * 4);
                    const float4 v0 = *(const float4*)(vs + lane * 4);
                    const float4 v1 = *(const float4*)(vs + 128 + lane * 4);
                    float s = v0.x * tanhf(p0.x + q0.x) + v0.y * tanhf(p0.y + q0.y)
                            + v0.z * tanhf(p0.z + q0.z) + v0.w * tanhf(p0.w + q0.w)
                            + v1.x * tanhf(p1.x + q1.x) + v1.y * tanhf(p1.y + q1.y)
                            + v1.z * tanhf(p1.z + q1.z) + v1.w * tanhf(p1.w + q1.w);
#pragma unroll
                    for (int off = 16; off > 0; off >>= 1)
                        s += __shfl_down_sync(0xffffffffu, s, off);
                    s = __shfl_sync(0xffffffffu, s, 0);
                    if (s > best) { best = s; bi = pos; }
                }
                if (lane == 0) { rs[wp2] = best; ri[wp2] = bi; }
                __syncthreads();
                if (tid == 0) {
                    float bb = rs[0]; int bx = ri[0];
#pragma unroll
                    for (int w = 1; w < 16; w++)
                        if (rs[w] > bb || (rs[w] == bb && ri[w] < bx)) { bb = rs[w]; bx = ri[w]; }
                    bond_s = bx;
                    if (r == 0) out[(size_t)bx * BB + b] = 1.0f;
                }
                __syncthreads();
            }
        }

        unsigned long long aa = 0ull, ab2 = 0ull;
        const ulonglong2* h0 = (const ulonglong2*)&hs[p][q * 64];
#pragma unroll
        for (int i = 0; i < 16; i++) {
            ulonglong2 x0 = h0[i];
            aa  = fma2(x0.x, w2[2*i], aa);
            ab2 = fma2(x0.y, w2[2*i+1], ab2);
        }
        float2 u = unpk(fma2(splat2(1.f), aa, ab2));
        zp[q][lr] = u.x + u.y;
        __syncthreads();

        if (upd) {
            float z[4];
#pragma unroll
            for (int g = 0; g < 4; g++) {
                int l = g * 32 + tid;
                z[g] = zp[0][l] + zp[1][l] + zp[2][l] + zp[3][l] + gv4[g] + bias4[g];
            }
            float iv = sigf(z[0]), fv = sigf(z[1]);
            float gg = tanhf(z[2]), ov = sigf(z[3]);
            c = fv * c + iv * gg;
            float h = ov * tanhf(c);
            int k = r * 32 + tid;
            unsigned int base = smem_u32(&hs[1 - p][k]);
#pragma unroll
            for (int cta = 0; cta < 8; cta++) st_cluster_f32(base, cta, h);
        }
        cluster_arrive();
        p ^= 1;
    }
    cluster_wait();   // h_{S-1} visible

    if (SS - 1 == bond_s) {   // trailing decision at the last step
        int td = SS - 1;
        {
            int j = tid & 255, kh = tid >> 8;
            const float* w4p = W4 + (size_t)(kh * 128) * WT_ + j;
            const float* hh = &hs[p][kh * 128];
            float acc = 0.f;
#pragma unroll 4
            for (int k = 0; k < 128; ++k) acc += hh[k] * w4p[(size_t)k * WT_];
            qp[kh][j] = acc;
        }
        __syncthreads();
        if (tid < 256)
            qv[tid] = qp[0][tid] + qp[1][tid] + b3[((size_t)(b * SS + td)) * WT_ + tid];
        __syncthreads();
        // only position td remains (pos >= td and pos < SS)
        if (tid < 32) {
            const float* Pr = P + ((size_t)(b * SS + td)) * WT_;
            float s = 0.f;
            for (int k = tid; k < WT_; k += 32)
                s += vs[k] * tanhf(Pr[k] + qv[k]);
#pragma unroll
            for (int off = 16; off > 0; off >>= 1)
                s += __shfl_down_sync(0xffffffffu, s, off);
            if (tid == 0 && r == 0) out[(size_t)td * BB + b] = 1.0f;
        }
    }
}

extern "C" void kernel_launch(void* const* d_in, const int* in_sizes, int n_in,
                              void* d_out, int out_size) {
    const float* x        = (const float*)d_in[0];
    const float* eWih_f   = (const float*)d_in[1];
    const float* eWhh_f   = (const float*)d_in[2];
    const float* eb_f     = (const float*)d_in[3];
    const float* eWih_b   = (const float*)d_in[4];
    const float* eWhh_b   = (const float*)d_in[5];
    const float* eb_b     = (const float*)d_in[6];
    const float* dWih     = (const float*)d_in[7];
    const float* dWhh     = (const float*)d_in[8];
    const float* db       = (const float*)d_in[9];
    const float* W1       = (const float*)d_in[10];
    const float* W2       = (const float*)d_in[11];
    const float* W3       = (const float*)d_in[12];
    const float* W4       = (const float*)d_in[13];
    const float* vt1      = (const float*)d_in[14];
    float* out = (float*)d_out;

    float *Af, *Ab, *G, *hn, *hb, *P, *b3, *WTf, *WTb, *WTd;
    cudaGetSymbolAddress((void**)&Af,  g_Af);
    cudaGetSymbolAddress((void**)&Ab,  g_Ab);
    cudaGetSymbolAddress((void**)&G,   g_G);
    cudaGetSymbolAddress((void**)&hn,  g_hn);
    cudaGetSymbolAddress((void**)&hb,  g_hb);
    cudaGetSymbolAddress((void**)&P,   g_P);
    cudaGetSymbolAddress((void**)&b3,  g_b3);
    cudaGetSymbolAddress((void**)&WTf, g_WTf);
    cudaGetSymbolAddress((void**)&WTb, g_WTb);
    cudaGetSymbolAddress((void**)&WTd, g_WTd);

    dim3 tb(32, 32), tg(G4 / 32, HH / 32);
    transpose_w<<<tg, tb>>>(eWhh_f, WTf);
    transpose_w<<<tg, tb>>>(eWhh_b, WTb);
    transpose_w<<<tg, tb>>>(dWhh,   WTd);

    const int M = BB * SS;
    sgemm_ms<<<dim3(G4 / 128, M / 128), 256>>>(x, 0, 0, eWih_f, 0, 0, Af, M, G4, 1);
    sgemm_ms<<<dim3(G4 / 128, M / 128), 256>>>(x, 0, 0, eWih_b, 0, 0, Ab, M, G4, 1);
    sgemm_ms<<<dim3(WT_ / 128, M / 128), 256>>>(x, 0, 0, W3, 0, 0, b3, M, WT_, 1);

    lstm_enc<<<128, 512>>>(Af, Ab, WTf, WTb, eb_f, eb_b, hn, hb);

    sgemm_ms<<<dim3(G4 / 128, M / 128), 256>>>(x, hn, 0, dWih, dWih + EE * G4, 0,
                                               G, M, G4, 2);
    sgemm_ms<<<dim3(WT_ / 128, M / 128), 256>>>(hn, hb, x, W1, W1 + HH * WT_, W2,
                                                P, M, WT_, 3);

    lstm_dec<<<128, 512>>>(G, WTd, db, hn, P, b3, W4, vt1, out);
}